// round 6
// baseline (speedup 1.0000x reference)
#include <cuda_runtime.h>
#include <cuda_bf16.h>
#include <cstdint>

// PhysicsRouter v6: one 16KB contiguous bulk copy per pipeline stage.
// logits = X @ W^T + mass*bias; softmax; top-2; aux loss.
// X [16384, 4096] f32, mass [16384], W [4, 4096], bias [4].
// Output (f32): [0,65536) logits | [65536,98304) top_k_idx | [98304] aux | [98305,131073) top_k_w
//
// Rounds 4/5 plateaued at ~46% DRAM because copies were issued as many small
// commands (16B cp.async / 512B bulk) and the copy-COMMAND rate (~46cyc/cmd at
// the TMA front end) capped throughput at ~3.7 TB/s. Here a stage is one full
// token row (16 KB, contiguous) = ONE cp.async.bulk command. 8 warps split the
// row by columns; per-token partials are combined through smem in the epilogue.

#define C_DIM 4096
#define E_DIM 4
#define N_TOK 16384
#define TPB 16                          // tokens per block == stages per block
#define BLOCK_THREADS 256
#define NWARPS 8
#define GRID_BLOCKS (N_TOK / TPB)       // 1024
#define DEPTH 3
#define ROW_BYTES (C_DIM * 4)           // 16384
#define COLS_PER_WARP (C_DIM / NWARPS)  // 512
#define CHUNKS 4                        // 4 x 128 cols per warp

// dynamic smem layout
#define SX_BYTES (DEPTH * ROW_BYTES)               // 49152
#define OFF_MBAR  SX_BYTES                          // DEPTH x 8
#define OFF_PART  (OFF_MBAR + 64)                   // s_part[TPB][NWARPS] float4 = 2048
#define OFF_IMP   (OFF_PART + TPB * NWARPS * 16)    // s_imp[NWARPS][4] = 128
#define OFF_FLAG  (OFF_IMP + NWARPS * 16)
#define SMEM_SIZE (OFF_FLAG + 16)

__device__ float g_partial[GRID_BLOCKS][E_DIM];
__device__ unsigned int g_count = 0;    // wraps to 0 each full grid -> graph-replay safe

__device__ __forceinline__ uint32_t smem_u32(const void* p) {
    return (uint32_t)__cvta_generic_to_shared(p);
}
__device__ __forceinline__ void mbar_init(uint32_t a, uint32_t cnt) {
    asm volatile("mbarrier.init.shared.b64 [%0], %1;" :: "r"(a), "r"(cnt) : "memory");
}
__device__ __forceinline__ void mbar_expect_tx(uint32_t a, uint32_t bytes) {
    asm volatile("mbarrier.arrive.expect_tx.shared.b64 _, [%0], %1;"
                 :: "r"(a), "r"(bytes) : "memory");
}
__device__ __forceinline__ void bulk_g2s(uint32_t dst, const void* src,
                                         uint32_t bytes, uint32_t mb) {
    asm volatile(
        "cp.async.bulk.shared::cluster.global.mbarrier::complete_tx::bytes "
        "[%0], [%1], %2, [%3];"
        :: "r"(dst), "l"(src), "r"(bytes), "r"(mb) : "memory");
}
__device__ __forceinline__ void mbar_wait(uint32_t a, uint32_t parity) {
    asm volatile(
        "{\n\t"
        ".reg .pred P;\n\t"
        "WAIT_%=:\n\t"
        "mbarrier.try_wait.parity.acquire.cta.shared::cta.b64 P, [%0], %1, 0x989680;\n\t"
        "@P bra DONE_%=;\n\t"
        "bra WAIT_%=;\n\t"
        "DONE_%=:\n\t"
        "}"
        :: "r"(a), "r"(parity) : "memory");
}

__global__ __launch_bounds__(BLOCK_THREADS, 4)
void router_v6(const float* __restrict__ X,
               const float* __restrict__ mass,
               const float* __restrict__ W,
               const float* __restrict__ bias,
               float* __restrict__ out)
{
    extern __shared__ char smem[];
    float* sx = (float*)smem;                                  // [DEPTH][C_DIM]
    unsigned long long* mbar = (unsigned long long*)(smem + OFF_MBAR);
    float4* s_part = (float4*)(smem + OFF_PART);               // [TPB][NWARPS]
    float*  s_imp  = (float*)(smem + OFF_IMP);                 // [NWARPS][4]
    int*    s_flag = (int*)(smem + OFF_FLAG);

    const int tid  = threadIdx.x;
    const int warp = tid >> 5;
    const int lane = tid & 31;
    const long token0 = (long)blockIdx.x * TPB;
    const float* xbase = X + token0 * (long)C_DIM;

    if (tid < DEPTH) mbar_init(smem_u32(&mbar[tid]), 1);
    __syncthreads();

    // ---- prologue: 2 stages in flight ----
    if (tid == 0) {
#pragma unroll
        for (int s = 0; s < DEPTH - 1; s++) {
            const uint32_t mb = smem_u32(&mbar[s]);
            mbar_expect_tx(mb, ROW_BYTES);
            bulk_g2s(smem_u32(&sx[s * C_DIM]), xbase + (long)s * C_DIM,
                     ROW_BYTES, mb);
        }
    }

    // ---- mainloop: stage s == token s ----
#pragma unroll 1
    for (int s = 0; s < TPB; s++) {
        const int buf = s % DEPTH;
        mbar_wait(smem_u32(&mbar[buf]), (s / DEPTH) & 1);

        const float* xrow = &sx[buf * C_DIM + warp * COLS_PER_WARP];
        float acc[E_DIM] = {0.f, 0.f, 0.f, 0.f};
#pragma unroll
        for (int c = 0; c < CHUNKS; c++) {
            const int col = c * 128 + lane * 4;
            const float4 x = *(const float4*)(xrow + col);
            const int gcol = warp * COLS_PER_WARP + col;
#pragma unroll
            for (int e = 0; e < E_DIM; e++) {
                const float4 g = __ldg((const float4*)(W + e * C_DIM + gcol));
                float a = acc[e];
                a = fmaf(x.x, g.x, a);
                a = fmaf(x.y, g.y, a);
                a = fmaf(x.z, g.z, a);
                a = fmaf(x.w, g.w, a);
                acc[e] = a;
            }
        }

        // butterfly-reduce the 4-expert partial across the warp
#pragma unroll
        for (int e = 0; e < E_DIM; e++)
#pragma unroll
            for (int sh = 16; sh > 0; sh >>= 1)
                acc[e] += __shfl_xor_sync(0xFFFFFFFFu, acc[e], sh);
        if (lane == 0) {
            float4 v; v.x = acc[0]; v.y = acc[1]; v.z = acc[2]; v.w = acc[3];
            s_part[s * NWARPS + warp] = v;
        }

        __syncthreads();               // everyone done with buf before refill

        const int ns = s + DEPTH - 1;
        if (tid == 0 && ns < TPB) {
            const int nb = ns % DEPTH;
            const uint32_t mb = smem_u32(&mbar[nb]);
            mbar_expect_tx(mb, ROW_BYTES);
            bulk_g2s(smem_u32(&sx[nb * C_DIM]), xbase + (long)ns * C_DIM,
                     ROW_BYTES, mb);
        }
    }

    // ---- epilogue: warp 0, lane t < TPB handles token t ----
    float p[E_DIM] = {0.f, 0.f, 0.f, 0.f};
    if (warp == 0) {
        if (lane < TPB) {
            float q0 = 0.f, q1 = 0.f, q2 = 0.f, q3 = 0.f;
#pragma unroll
            for (int w = 0; w < NWARPS; w++) {
                const float4 v = s_part[lane * NWARPS + w];
                q0 += v.x; q1 += v.y; q2 += v.z; q3 += v.w;
            }
            const long token = token0 + lane;
            const float m = __ldg(mass + token);
            const float4 b = __ldg((const float4*)bias);
            q0 = fmaf(m, b.x, q0);
            q1 = fmaf(m, b.y, q1);
            q2 = fmaf(m, b.z, q2);
            q3 = fmaf(m, b.w, q3);

            float4 lo; lo.x = q0; lo.y = q1; lo.z = q2; lo.w = q3;
            *(float4*)(out + token * E_DIM) = lo;

            const float mx = fmaxf(fmaxf(q0, q1), fmaxf(q2, q3));
            p[0] = expf(q0 - mx);
            p[1] = expf(q1 - mx);
            p[2] = expf(q2 - mx);
            p[3] = expf(q3 - mx);
            const float inv = 1.0f / (p[0] + p[1] + p[2] + p[3]);
            p[0] *= inv; p[1] *= inv; p[2] *= inv; p[3] *= inv;

            // top-2, lowest-index tie break (strict > keeps earlier index)
            int i1 = 0; float v1 = p[0];
#pragma unroll
            for (int e = 1; e < E_DIM; e++)
                if (p[e] > v1) { v1 = p[e]; i1 = e; }
            int i2 = -1; float v2 = -1.0f;
#pragma unroll
            for (int e = 0; e < E_DIM; e++)
                if (e != i1 && p[e] > v2) { v2 = p[e]; i2 = e; }

            float* out_idx = out + (long)N_TOK * E_DIM;
            float* out_w   = out + (long)N_TOK * E_DIM + (long)N_TOK * 2 + 1;
            out_idx[token * 2 + 0] = (float)i1;
            out_idx[token * 2 + 1] = (float)i2;
            out_w[token * 2 + 0]   = v1;
            out_w[token * 2 + 1]   = v2;
        }

        // expert importance: butterfly over warp 0 (lanes >= TPB contribute 0)
#pragma unroll
        for (int e = 0; e < E_DIM; e++)
#pragma unroll
            for (int sh = 16; sh > 0; sh >>= 1)
                p[e] += __shfl_xor_sync(0xFFFFFFFFu, p[e], sh);

        if (lane == 0) {
#pragma unroll
            for (int e = 0; e < E_DIM; e++)
                g_partial[blockIdx.x][e] = p[e];
            __threadfence();
            const unsigned int v = atomicInc(&g_count, GRID_BLOCKS - 1);
            s_flag[0] = (v == GRID_BLOCKS - 1) ? 1 : 0;
        }
    }
    __syncthreads();

    // ---- last block finalizes aux loss ----
    if (s_flag[0]) {
        __shared__ double s_sum[BLOCK_THREADS];
        const int e = tid & 3;
        const int chunk = tid >> 2;                           // 0..63
        const int per = GRID_BLOCKS / (BLOCK_THREADS / 4);    // 16
        double s = 0.0;
        for (int j = chunk * per; j < (chunk + 1) * per; j++)
            s += (double)g_partial[j][e];
        s_sum[tid] = s;
        __syncthreads();
        if (tid < E_DIM) {
            double imp = 0.0;
#pragma unroll
            for (int k = 0; k < BLOCK_THREADS / 4; k++)
                imp += s_sum[e + 4 * k];                      // e == tid here
            s_sum[tid] = imp;
        }
        __syncthreads();
        if (tid == 0) {
            const double target = (double)N_TOK / (double)E_DIM;
            double loss = 0.0;
#pragma unroll
            for (int k = 0; k < E_DIM; k++) {
                const double d = s_sum[k] - target;
                loss += d * d;
            }
            out[(long)N_TOK * E_DIM + (long)N_TOK * 2] = (float)(loss / E_DIM);
        }
    }
}

extern "C" void kernel_launch(void* const* d_in, const int* in_sizes, int n_in,
                              void* d_out, int out_size)
{
    const float* X    = (const float*)d_in[0];
    const float* mass = (const float*)d_in[1];
    const float* W    = (const float*)d_in[2];
    const float* bias = (const float*)d_in[3];
    float* out = (float*)d_out;

    cudaFuncSetAttribute(router_v6, cudaFuncAttributeMaxDynamicSharedMemorySize,
                         SMEM_SIZE);
    router_v6<<<GRID_BLOCKS, BLOCK_THREADS, SMEM_SIZE>>>(X, mass, W, bias, out);
}

// round 7
// speedup vs baseline: 1.1046x; 1.1046x over previous
#include <cuda_runtime.h>
#include <cuda_bf16.h>
#include <cstdint>

// PhysicsRouter v7: gate-in-registers + 64KB bulk stages, minimal barriers.
// logits = X @ W^T + mass*bias; softmax; top-2; aux loss.
// X [16384, 4096] f32, mass [16384], W [4, 4096], bias [4].
// Output (f32): [0,65536) logits | [65536,98304) top_k_idx | [98304] aux | [98305,131073) top_k_w
//
// Rounds 4-6 post-mortem: the copies were fine; the CONSUMERS were the
// bottleneck (per-stage block barriers x 16-32 stages, and 4B of gate L1
// traffic per 1B of X). Here each warp owns a FIXED 256-col slice, so its 8
// gate float4s live in registers for the whole kernel (zero gate loads in the
// mainloop), and a stage is 4 contiguous token rows = ONE 64KB cp.async.bulk,
// giving only 4 stages (8 barriers) per block.

#define C_DIM 4096
#define E_DIM 4
#define N_TOK 16384
#define TPB 16                           // tokens per block
#define BLOCK_THREADS 512
#define NWARPS 16
#define GRID_BLOCKS (N_TOK / TPB)        // 1024
#define ROWS_PER_STAGE 4
#define NSTAGES (TPB / ROWS_PER_STAGE)   // 4
#define DEPTH 2
#define STAGE_FLOATS (ROWS_PER_STAGE * C_DIM)       // 16384 floats
#define STAGE_BYTES  (STAGE_FLOATS * 4)             // 65536
#define WCOLS 256                        // columns per warp (fixed slice)
#define WCHUNKS (WCOLS / 128)            // 2

// dynamic smem layout
#define OFF_MBAR  (DEPTH * STAGE_BYTES)             // 131072
#define OFF_PART  (OFF_MBAR + 64)                   // s_part[TPB][NWARPS] float4
#define OFF_FLAG  (OFF_PART + TPB * NWARPS * 16)
#define SMEM_SIZE (OFF_FLAG + 16)

__device__ float g_partial[GRID_BLOCKS][E_DIM];
__device__ unsigned int g_count = 0;     // wraps to 0 each full grid -> graph-replay safe

__device__ __forceinline__ uint32_t smem_u32(const void* p) {
    return (uint32_t)__cvta_generic_to_shared(p);
}
__device__ __forceinline__ void mbar_init(uint32_t a, uint32_t cnt) {
    asm volatile("mbarrier.init.shared.b64 [%0], %1;" :: "r"(a), "r"(cnt) : "memory");
}
__device__ __forceinline__ void mbar_expect_tx(uint32_t a, uint32_t bytes) {
    asm volatile("mbarrier.arrive.expect_tx.shared.b64 _, [%0], %1;"
                 :: "r"(a), "r"(bytes) : "memory");
}
__device__ __forceinline__ void bulk_g2s(uint32_t dst, const void* src,
                                         uint32_t bytes, uint32_t mb) {
    asm volatile(
        "cp.async.bulk.shared::cluster.global.mbarrier::complete_tx::bytes "
        "[%0], [%1], %2, [%3];"
        :: "r"(dst), "l"(src), "r"(bytes), "r"(mb) : "memory");
}
__device__ __forceinline__ void mbar_wait(uint32_t a, uint32_t parity) {
    asm volatile(
        "{\n\t"
        ".reg .pred P;\n\t"
        "WAIT_%=:\n\t"
        "mbarrier.try_wait.parity.acquire.cta.shared::cta.b64 P, [%0], %1, 0x989680;\n\t"
        "@P bra DONE_%=;\n\t"
        "bra WAIT_%=;\n\t"
        "DONE_%=:\n\t"
        "}"
        :: "r"(a), "r"(parity) : "memory");
}

__global__ __launch_bounds__(BLOCK_THREADS, 1)
void router_v7(const float* __restrict__ X,
               const float* __restrict__ mass,
               const float* __restrict__ W,
               const float* __restrict__ bias,
               float* __restrict__ out)
{
    extern __shared__ char smem[];
    float* sx = (float*)smem;                                    // [DEPTH][STAGE_FLOATS]
    unsigned long long* mbar = (unsigned long long*)(smem + OFF_MBAR);
    float4* s_part = (float4*)(smem + OFF_PART);                 // [TPB][NWARPS]
    int*    s_flag = (int*)(smem + OFF_FLAG);

    const int tid  = threadIdx.x;
    const int warp = tid >> 5;
    const int lane = tid & 31;
    const long token0 = (long)blockIdx.x * TPB;
    const float* xbase = X + token0 * (long)C_DIM;

    if (tid < DEPTH) mbar_init(smem_u32(&mbar[tid]), 1);
    __syncthreads();

    // ---- prologue: issue both buffers ----
    if (tid == 0) {
#pragma unroll
        for (int s = 0; s < DEPTH; s++) {
            const uint32_t mb = smem_u32(&mbar[s]);
            mbar_expect_tx(mb, STAGE_BYTES);
            bulk_g2s(smem_u32(&sx[s * STAGE_FLOATS]),
                     xbase + (long)s * STAGE_FLOATS, STAGE_BYTES, mb);
        }
    }

    // ---- preload this warp's gate slice into registers (overlaps copy 0) ----
    // warp w owns columns [w*256, w*256+256) for the whole kernel.
    float4 g[WCHUNKS][E_DIM];
#pragma unroll
    for (int c = 0; c < WCHUNKS; c++) {
        const int col = warp * WCOLS + c * 128 + lane * 4;
#pragma unroll
        for (int e = 0; e < E_DIM; e++)
            g[c][e] = __ldg((const float4*)(W + e * C_DIM + col));
    }

    // ---- mainloop: 4 stages, each = 4 token rows ----
#pragma unroll 1
    for (int s = 0; s < NSTAGES; s++) {
        const int buf = s % DEPTH;
        mbar_wait(smem_u32(&mbar[buf]), (s / DEPTH) & 1);

        float acc[ROWS_PER_STAGE][E_DIM];
#pragma unroll
        for (int r = 0; r < ROWS_PER_STAGE; r++)
#pragma unroll
            for (int e = 0; e < E_DIM; e++) acc[r][e] = 0.0f;

#pragma unroll
        for (int c = 0; c < WCHUNKS; c++) {
            const int scol = warp * WCOLS + c * 128 + lane * 4;
#pragma unroll
            for (int r = 0; r < ROWS_PER_STAGE; r++) {
                const float4 x = *(const float4*)&sx[buf * STAGE_FLOATS + r * C_DIM + scol];
#pragma unroll
                for (int e = 0; e < E_DIM; e++) {
                    float a = acc[r][e];
                    a = fmaf(x.x, g[c][e].x, a);
                    a = fmaf(x.y, g[c][e].y, a);
                    a = fmaf(x.z, g[c][e].z, a);
                    a = fmaf(x.w, g[c][e].w, a);
                    acc[r][e] = a;
                }
            }
        }

        // butterfly-reduce the 16 partials across the warp
#pragma unroll
        for (int r = 0; r < ROWS_PER_STAGE; r++)
#pragma unroll
            for (int e = 0; e < E_DIM; e++)
#pragma unroll
                for (int sh = 16; sh > 0; sh >>= 1)
                    acc[r][e] += __shfl_xor_sync(0xFFFFFFFFu, acc[r][e], sh);

        if (lane == 0) {
#pragma unroll
            for (int r = 0; r < ROWS_PER_STAGE; r++) {
                float4 v; v.x = acc[r][0]; v.y = acc[r][1]; v.z = acc[r][2]; v.w = acc[r][3];
                s_part[(s * ROWS_PER_STAGE + r) * NWARPS + warp] = v;
            }
        }

        __syncthreads();            // all warps done with buf before refill

        const int ns = s + DEPTH;
        if (tid == 0 && ns < NSTAGES) {
            const uint32_t mb = smem_u32(&mbar[buf]);
            mbar_expect_tx(mb, STAGE_BYTES);
            bulk_g2s(smem_u32(&sx[buf * STAGE_FLOATS]),
                     xbase + (long)ns * STAGE_FLOATS, STAGE_BYTES, mb);
        }
    }

    // ---- epilogue: warp 0, lane t < TPB handles token t ----
    float p[E_DIM] = {0.f, 0.f, 0.f, 0.f};
    if (warp == 0) {
        if (lane < TPB) {
            float q0 = 0.f, q1 = 0.f, q2 = 0.f, q3 = 0.f;
#pragma unroll
            for (int w = 0; w < NWARPS; w++) {
                const float4 v = s_part[lane * NWARPS + w];
                q0 += v.x; q1 += v.y; q2 += v.z; q3 += v.w;
            }
            const long token = token0 + lane;
            const float m = __ldg(mass + token);
            const float4 b = __ldg((const float4*)bias);
            q0 = fmaf(m, b.x, q0);
            q1 = fmaf(m, b.y, q1);
            q2 = fmaf(m, b.z, q2);
            q3 = fmaf(m, b.w, q3);

            float4 lo; lo.x = q0; lo.y = q1; lo.z = q2; lo.w = q3;
            *(float4*)(out + token * E_DIM) = lo;

            const float mx = fmaxf(fmaxf(q0, q1), fmaxf(q2, q3));
            p[0] = expf(q0 - mx);
            p[1] = expf(q1 - mx);
            p[2] = expf(q2 - mx);
            p[3] = expf(q3 - mx);
            const float inv = 1.0f / (p[0] + p[1] + p[2] + p[3]);
            p[0] *= inv; p[1] *= inv; p[2] *= inv; p[3] *= inv;

            // top-2, lowest-index tie break (strict > keeps earlier index)
            int i1 = 0; float v1 = p[0];
#pragma unroll
            for (int e = 1; e < E_DIM; e++)
                if (p[e] > v1) { v1 = p[e]; i1 = e; }
            int i2 = -1; float v2 = -1.0f;
#pragma unroll
            for (int e = 0; e < E_DIM; e++)
                if (e != i1 && p[e] > v2) { v2 = p[e]; i2 = e; }

            float* out_idx = out + (long)N_TOK * E_DIM;
            float* out_w   = out + (long)N_TOK * E_DIM + (long)N_TOK * 2 + 1;
            out_idx[token * 2 + 0] = (float)i1;
            out_idx[token * 2 + 1] = (float)i2;
            out_w[token * 2 + 0]   = v1;
            out_w[token * 2 + 1]   = v2;
        }

        // expert importance: butterfly over warp 0 (lanes >= TPB contribute 0)
#pragma unroll
        for (int e = 0; e < E_DIM; e++)
#pragma unroll
            for (int sh = 16; sh > 0; sh >>= 1)
                p[e] += __shfl_xor_sync(0xFFFFFFFFu, p[e], sh);

        if (lane == 0) {
#pragma unroll
            for (int e = 0; e < E_DIM; e++)
                g_partial[blockIdx.x][e] = p[e];
            __threadfence();
            const unsigned int v = atomicInc(&g_count, GRID_BLOCKS - 1);
            s_flag[0] = (v == GRID_BLOCKS - 1) ? 1 : 0;
        }
    }
    __syncthreads();

    // ---- last block finalizes aux loss ----
    if (s_flag[0]) {
        __shared__ double s_sum[BLOCK_THREADS];
        const int e = tid & 3;
        const int chunk = tid >> 2;                            // 0..127
        const int per = GRID_BLOCKS / (BLOCK_THREADS / 4);     // 8
        double s = 0.0;
        for (int j = chunk * per; j < (chunk + 1) * per; j++)
            s += (double)g_partial[j][e];
        s_sum[tid] = s;
        __syncthreads();
        if (tid < E_DIM) {
            double imp = 0.0;
#pragma unroll
            for (int k = 0; k < BLOCK_THREADS / 4; k++)
                imp += s_sum[e + 4 * k];                       // e == tid here
            s_sum[tid] = imp;
        }
        __syncthreads();
        if (tid == 0) {
            const double target = (double)N_TOK / (double)E_DIM;
            double loss = 0.0;
#pragma unroll
            for (int k = 0; k < E_DIM; k++) {
                const double d = s_sum[k] - target;
                loss += d * d;
            }
            out[(long)N_TOK * E_DIM + (long)N_TOK * 2] = (float)(loss / E_DIM);
        }
    }
}

extern "C" void kernel_launch(void* const* d_in, const int* in_sizes, int n_in,
                              void* d_out, int out_size)
{
    const float* X    = (const float*)d_in[0];
    const float* mass = (const float*)d_in[1];
    const float* W    = (const float*)d_in[2];
    const float* bias = (const float*)d_in[3];
    float* out = (float*)d_out;

    cudaFuncSetAttribute(router_v7, cudaFuncAttributeMaxDynamicSharedMemorySize,
                         SMEM_SIZE);
    router_v7<<<GRID_BLOCKS, BLOCK_THREADS, SMEM_SIZE>>>(X, mass, W, bias, out);
}